// round 3
// baseline (speedup 1.0000x reference)
#include <cuda_runtime.h>

// ============================================================================
// PillarFeatureNet: augment -> Linear(9->64) -> BN(batch stats) -> ReLU ->
// masked max over P -> zero empty voxels.
//
// Exact algebraic restructuring:
//  - cluster mean per reference = (sum over ALL 32 points of xyz) / max(k,1)
//  - BN mean/var per channel from feature moments: mean=W·S/NP,
//    E[x^2]=W^T M W / NP, with S(9), M(9x9) built from 54 global accumulators.
//  - 9->64 linear folds into 4->64 linear + per-voxel per-channel offset.
//  - relu(max) == max(relu) over valid points.
// ============================================================================

#define MAX_N 60000
#define BLOCK 256
#define GRID  592
#define NSTAT 54

// stats layout:
// [0..3]   G1_i   = sum_valid v_i
// [4..13]  G2_ij  = sum_valid v_i v_j (00,01,02,03,11,12,13,22,23,33)
// [14..25] U_ij   = sum_n m_i sv_j   (i:0..2, j:0..3) at 14+i*4+j   (k>0 voxels)
// [26..31] V_ij   = sum_n sa_i m_j   (sym 3x3: 00,01,02,11,12,22)
// [32..34] Wx_i   = sum_n sa_i px    (i:0..2)
// [35..37] Wy_i   = sum_n sa_i py
// [38..40] Ksa_i  = sum_n sa_i       (= sum k*m_i)
// [41..44] Qx_j   = sum_n px sv_j    (j:0..3)
// [45..48] Qy_j   = sum_n py sv_j
// [49..51] Rxx,Rxy,Ryy = sum_n k px^2, k px py, k py^2
// [52..53] Lx,Ly  = sum_n k px, k py
__device__ float  g_stats[NSTAT];
__device__ float  g_params[10 * 64];   // rows: A0..A3, B0..B4, T
__device__ float4 g_meta[MAX_N];       // (m0, m1, m2, k)

__device__ __forceinline__ float wsum(float x) {
#pragma unroll
    for (int o = 16; o; o >>= 1) x += __shfl_xor_sync(0xffffffffu, x, o);
    return x;
}

__global__ void k_zero() {
    if (threadIdx.x < NSTAT) g_stats[threadIdx.x] = 0.0f;
}

// ---------------------------------------------------------------------------
// Pass 1: global moments + per-voxel meta. One warp per voxel; lane = point.
// ---------------------------------------------------------------------------
__global__ void __launch_bounds__(BLOCK) k_pass1(
    const float4* __restrict__ vox, const int* __restrict__ npts,
    const int* __restrict__ coors, int N)
{
    const int lane   = threadIdx.x & 31;
    const int wid    = threadIdx.x >> 5;
    const int warp   = blockIdx.x * (BLOCK >> 5) + wid;
    const int nwarps = gridDim.x * (BLOCK >> 5);

    float a[14];
#pragma unroll
    for (int i = 0; i < 14; i++) a[i] = 0.0f;
    float pv[40];
#pragma unroll
    for (int i = 0; i < 40; i++) pv[i] = 0.0f;

    for (int n = warp; n < N; n += nwarps) {
        const int k = __ldg(&npts[n]);
        const float4 v = vox[(size_t)n * 32 + lane];
        float4 u = v;                               // masked copy
        if (lane >= k) { u.x = 0.f; u.y = 0.f; u.z = 0.f; u.w = 0.f; }

        // lane-private global raw moments (valid points only)
        a[0]  += u.x;        a[1]  += u.y;        a[2]  += u.z;        a[3]  += u.w;
        a[4]  += u.x * u.x;  a[5]  += u.x * u.y;  a[6]  += u.x * u.z;  a[7]  += u.x * u.w;
        a[8]  += u.y * u.y;  a[9]  += u.y * u.z;  a[10] += u.y * u.w;
        a[11] += u.z * u.z;  a[12] += u.z * u.w;  a[13] += u.w * u.w;

        // unmasked all-point xyz sums (reference's points_mean numerator)
        const float sa0 = wsum(v.x), sa1 = wsum(v.y), sa2 = wsum(v.z);
        // masked valid-point sums
        const float sv0 = wsum(u.x), sv1 = wsum(u.y), sv2 = wsum(u.z), sv3 = wsum(u.w);

        if (lane == 0) {
            if (k > 0) {
                const float kf  = (float)k;
                const float inv = 1.0f / kf;
                const float m0 = sa0 * inv, m1 = sa1 * inv, m2 = sa2 * inv;
                g_meta[n] = make_float4(m0, m1, m2, kf);
                const float px = (float)coors[4 * n + 1] * 0.1f + 0.05f - 20.0f;
                const float py = (float)coors[4 * n + 2] * 0.1f + 0.05f - 20.0f;
                // U_ij = m_i * sv_j
                pv[0]  += m0 * sv0;  pv[1]  += m0 * sv1;  pv[2]  += m0 * sv2;  pv[3]  += m0 * sv3;
                pv[4]  += m1 * sv0;  pv[5]  += m1 * sv1;  pv[6]  += m1 * sv2;  pv[7]  += m1 * sv3;
                pv[8]  += m2 * sv0;  pv[9]  += m2 * sv1;  pv[10] += m2 * sv2;  pv[11] += m2 * sv3;
                // V_ij = sa_i * m_j (symmetric)
                pv[12] += sa0 * m0;  pv[13] += sa0 * m1;  pv[14] += sa0 * m2;
                pv[15] += sa1 * m1;  pv[16] += sa1 * m2;  pv[17] += sa2 * m2;
                // Wx, Wy
                pv[18] += sa0 * px;  pv[19] += sa1 * px;  pv[20] += sa2 * px;
                pv[21] += sa0 * py;  pv[22] += sa1 * py;  pv[23] += sa2 * py;
                // Ksa
                pv[24] += sa0;       pv[25] += sa1;       pv[26] += sa2;
                // Qx, Qy
                pv[27] += px * sv0;  pv[28] += px * sv1;  pv[29] += px * sv2;  pv[30] += px * sv3;
                pv[31] += py * sv0;  pv[32] += py * sv1;  pv[33] += py * sv2;  pv[34] += py * sv3;
                // R, L
                pv[35] += kf * px * px;  pv[36] += kf * px * py;  pv[37] += kf * py * py;
                pv[38] += kf * px;       pv[39] += kf * py;
            } else {
                g_meta[n] = make_float4(0.0f, 0.0f, 0.0f, 0.0f);
            }
        }
    }

#pragma unroll
    for (int i = 0; i < 14; i++) a[i] = wsum(a[i]);

    __shared__ float red[BLOCK / 32][NSTAT];
    if (lane == 0) {
#pragma unroll
        for (int i = 0; i < 14; i++) red[wid][i] = a[i];
#pragma unroll
        for (int i = 0; i < 40; i++) red[wid][14 + i] = pv[i];
    }
    __syncthreads();
    if (threadIdx.x < NSTAT) {
        float s = 0.0f;
#pragma unroll
        for (int w = 0; w < BLOCK / 32; w++) s += red[w][threadIdx.x];
        atomicAdd(&g_stats[threadIdx.x], s);
    }
}

// ---------------------------------------------------------------------------
// Finalize: assemble S[9], M[9][9], BN affine, fold weights. 1 block x 64.
// ---------------------------------------------------------------------------
__global__ void k_finalize(const float* __restrict__ Wm, const float* __restrict__ gm,
                           const float* __restrict__ bt, float invNP)
{
    __shared__ float S[9];
    __shared__ float M[9][9];
    if (threadIdx.x == 0) {
        float st[NSTAT];
#pragma unroll
        for (int i = 0; i < NSTAT; i++) st[i] = g_stats[i];

        auto G2 = [&](int i, int j) -> float {
            if (i > j) { int t = i; i = j; j = t; }
            const int base[4] = {0, 4, 7, 9};
            return st[4 + base[i] + (j - i)];
        };
        auto U = [&](int i, int j) -> float { return st[14 + i * 4 + j]; };
        auto V = [&](int i, int j) -> float {
            int lo = i < j ? i : j, hi = i < j ? j : i;
            const int b3[3] = {0, 3, 5};
            return st[26 + b3[lo] + (hi - lo)];
        };
        const float* Wx = st + 32; const float* Wy = st + 35; const float* Ksa = st + 38;
        const float* Qx = st + 41; const float* Qy = st + 45;
        const float Rxx = st[49], Rxy = st[50], Ryy = st[51], Lx = st[52], Ly = st[53];

        S[0] = st[0]; S[1] = st[1]; S[2] = st[2]; S[3] = st[3];
        S[4] = st[0] - Ksa[0]; S[5] = st[1] - Ksa[1]; S[6] = st[2] - Ksa[2];
        S[7] = st[0] - Lx;     S[8] = st[1] - Ly;

        for (int i = 0; i < 4; i++)
            for (int j = 0; j < 4; j++) M[i][j] = G2(i, j);
        for (int j = 0; j < 3; j++)
            for (int i = 0; i < 4; i++) {
                const float m = G2(i, j) - U(j, i);
                M[i][4 + j] = m; M[4 + j][i] = m;
            }
        for (int i = 0; i < 3; i++)
            for (int j = 0; j < 3; j++)
                M[4 + i][4 + j] = G2(i, j) - U(i, j) - U(j, i) + V(i, j);
        for (int i = 0; i < 4; i++) {
            float m = G2(i, 0) - Qx[i]; M[i][7] = m; M[7][i] = m;
            m       = G2(i, 1) - Qy[i]; M[i][8] = m; M[8][i] = m;
        }
        for (int i = 0; i < 3; i++) {
            float m = G2(i, 0) - Qx[i] - U(i, 0) + Wx[i]; M[4 + i][7] = m; M[7][4 + i] = m;
            m       = G2(i, 1) - Qy[i] - U(i, 1) + Wy[i]; M[4 + i][8] = m; M[8][4 + i] = m;
        }
        M[7][7] = G2(0, 0) - 2.0f * Qx[0] + Rxx;
        M[7][8] = G2(0, 1) - Qx[1] - Qy[0] + Rxy; M[8][7] = M[7][8];
        M[8][8] = G2(1, 1) - 2.0f * Qy[1] + Ryy;
    }
    __syncthreads();

    const int o = threadIdx.x;
    if (o < 64) {
        float w[9];
#pragma unroll
        for (int j = 0; j < 9; j++) w[j] = Wm[o * 9 + j];
        float mean = 0.0f;
#pragma unroll
        for (int j = 0; j < 9; j++) mean += w[j] * S[j];
        mean *= invNP;
        float e2 = 0.0f;
#pragma unroll
        for (int i = 0; i < 9; i++) {
            float acc = 0.0f;
#pragma unroll
            for (int j = 0; j < 9; j++) acc += w[j] * M[i][j];
            e2 += w[i] * acc;
        }
        e2 *= invNP;
        const float var = e2 - mean * mean;
        const float sc  = gm[o] * rsqrtf(var + 1e-3f);
        const float sh  = bt[o] - mean * sc;

        g_params[0 * 64 + o] = sc * (w[0] + w[4] + w[7]);
        g_params[1 * 64 + o] = sc * (w[1] + w[5] + w[8]);
        g_params[2 * 64 + o] = sc * (w[2] + w[6]);
        g_params[3 * 64 + o] = sc * w[3];
        g_params[4 * 64 + o] = sc * w[4];
        g_params[5 * 64 + o] = sc * w[5];
        g_params[6 * 64 + o] = sc * w[6];
        g_params[7 * 64 + o] = sc * w[7];
        g_params[8 * 64 + o] = sc * w[8];
        g_params[9 * 64 + o] = sh;
    }
}

// ---------------------------------------------------------------------------
// Pass 2: one warp per voxel; lane handles channels (2*lane, 2*lane+1).
// ---------------------------------------------------------------------------
__global__ void __launch_bounds__(BLOCK) k_pass2(
    const float4* __restrict__ vox, const int* __restrict__ coors,
    float2* __restrict__ out, int N)
{
    const int lane   = threadIdx.x & 31;
    const int wid    = threadIdx.x >> 5;
    const int warp   = blockIdx.x * (BLOCK >> 5) + wid;
    const int nwarps = gridDim.x * (BLOCK >> 5);
    const int c      = lane * 2;

    const float A0a = g_params[0 * 64 + c], A0b = g_params[0 * 64 + c + 1];
    const float A1a = g_params[1 * 64 + c], A1b = g_params[1 * 64 + c + 1];
    const float A2a = g_params[2 * 64 + c], A2b = g_params[2 * 64 + c + 1];
    const float A3a = g_params[3 * 64 + c], A3b = g_params[3 * 64 + c + 1];
    const float B0a = g_params[4 * 64 + c], B0b = g_params[4 * 64 + c + 1];
    const float B1a = g_params[5 * 64 + c], B1b = g_params[5 * 64 + c + 1];
    const float B2a = g_params[6 * 64 + c], B2b = g_params[6 * 64 + c + 1];
    const float B3a = g_params[7 * 64 + c], B3b = g_params[7 * 64 + c + 1];
    const float B4a = g_params[8 * 64 + c], B4b = g_params[8 * 64 + c + 1];
    const float Ta  = g_params[9 * 64 + c], Tb  = g_params[9 * 64 + c + 1];

    __shared__ float4 pts[BLOCK / 32][32];
    const float NEG_INF = __int_as_float(0xff800000);

    for (int n = warp; n < N; n += nwarps) {
        const float4 meta = g_meta[n];
        const int k = (int)meta.w;
        if (k == 0) {
            out[(size_t)n * 32 + lane] = make_float2(0.0f, 0.0f);
            continue;
        }
        pts[wid][lane] = vox[(size_t)n * 32 + lane];

        const float px = (float)coors[4 * n + 1] * 0.1f + 0.05f - 20.0f;
        const float py = (float)coors[4 * n + 2] * 0.1f + 0.05f - 20.0f;

        float ta = B0a * meta.x;    ta = fmaf(B1a, meta.y, ta);
        ta = fmaf(B2a, meta.z, ta); ta = fmaf(B3a, px, ta); ta = fmaf(B4a, py, ta);
        const float offa = Ta - ta;
        float tb = B0b * meta.x;    tb = fmaf(B1b, meta.y, tb);
        tb = fmaf(B2b, meta.z, tb); tb = fmaf(B3b, px, tb); tb = fmaf(B4b, py, tb);
        const float offb = Tb - tb;

        __syncwarp();
        float ra = NEG_INF, rb = NEG_INF;
#pragma unroll 8
        for (int p = 0; p < k; p++) {
            const float4 u = pts[wid][p];
            const float ya = fmaf(u.x, A0a, fmaf(u.y, A1a, fmaf(u.z, A2a, fmaf(u.w, A3a, offa))));
            const float yb = fmaf(u.x, A0b, fmaf(u.y, A1b, fmaf(u.z, A2b, fmaf(u.w, A3b, offb))));
            ra = fmaxf(ra, ya);
            rb = fmaxf(rb, yb);
        }
        out[(size_t)n * 32 + lane] = make_float2(fmaxf(ra, 0.0f), fmaxf(rb, 0.0f));
        __syncwarp();
    }
}

// ---------------------------------------------------------------------------
extern "C" void kernel_launch(void* const* d_in, const int* in_sizes, int n_in,
                              void* d_out, int out_size)
{
    const float* voxels = (const float*)d_in[0];
    const int*   npts   = (const int*)d_in[1];
    const int*   coors  = (const int*)d_in[2];
    const float* W      = (const float*)d_in[3];
    const float* gamma  = (const float*)d_in[4];
    const float* beta   = (const float*)d_in[5];
    float*       out    = (float*)d_out;
    const int N = in_sizes[1];

    k_zero<<<1, 64>>>();
    k_pass1<<<GRID, BLOCK>>>((const float4*)voxels, npts, coors, N);
    k_finalize<<<1, 64>>>(W, gamma, beta, 1.0f / ((float)N * 32.0f));
    k_pass2<<<GRID, BLOCK>>>((const float4*)voxels, coors, (float2*)out, N);
}

// round 4
// speedup vs baseline: 1.0631x; 1.0631x over previous
#include <cuda_runtime.h>
#include <cstdint>

// ============================================================================
// PillarFeatureNet: augment -> Linear(9->64) -> BN(batch stats) -> ReLU ->
// masked max over P -> zero empty voxels.  (exact algebraic restructuring)
//
// pass1: raw/per-voxel moments (3 butterflies/voxel; U,Q accumulated per-lane
//        via broadcast m; scalar terms distributed 1/lane through smem).
//        Last block (atomic counter) finalizes BN params + self-resets state.
// pass2: folded 4->64 linear + offset, packed f32x2 over point pairs,
//        running max, relu at the end.
// ============================================================================

#define MAX_N 60000
#define BLOCK 256
#define GRID  592
#define NWARP (BLOCK / 32)
#define NSTAT 54

// stats layout:
// [0..13]  G1_i (4), G2_ij (10: 00,01,02,03,11,12,13,22,23,33)
// [14..25] U_ij   = sum m_i sv_j       (i:0..2, j:0..3) at 14+4i+j
// [26..29] Qx_j   = sum px sv_j
// [30..33] Qy_j   = sum py sv_j
// [34..39] V_ij   = sum sa_i m_j       (sym 3x3: 00,01,02,11,12,22)
// [40..42] Wx_i   = sum sa_i px
// [43..45] Wy_i   = sum sa_i py
// [46..48] Ksa_i  = sum sa_i
// [49..51] Rxx,Rxy,Ryy = sum k px^2, k px py, k py^2
// [52..53] Lx,Ly  = sum k px, k py
__device__ float    g_stats[NSTAT];       // zero at load; last block re-zeroes
__device__ unsigned g_count;              // zero at load; last block resets
__device__ float    g_params[10 * 64];    // rows: A0..A3, B0..B4, T
__device__ float4   g_meta[MAX_N];        // (m0, m1, m2, k)

// distributed scalar terms: lane t -> q[iA]*q[iB]; q = {m0,m1,m2,sa0,sa1,sa2,
// px,py,kpx,kpy,1,pad}.  Terms 0..19 -> stats 34..53; lanes 20..31 dummy.
__constant__ unsigned char c_iA[32] = {3,3,3,4,4,5, 3,4,5, 3,4,5, 3,4,5, 8,8,9, 8,9,
                                       10,10,10,10,10,10,10,10,10,10,10,10};
__constant__ unsigned char c_iB[32] = {0,1,2,1,2,2, 6,6,6, 7,7,7, 10,10,10, 6,7,7, 10,10,
                                       10,10,10,10,10,10,10,10,10,10,10,10};

__device__ __forceinline__ float wsum(float x) {
#pragma unroll
    for (int o = 16; o; o >>= 1) x += __shfl_xor_sync(0xffffffffu, x, o);
    return x;
}

// packed f32x2 helpers
#define FMA2(d, a, b, c) asm("fma.rn.f32x2 %0, %1, %2, %3;" : "=l"(d) : "l"(a), "l"(b), "l"(c))
#define PACK2(d, lo, hi) asm("mov.b64 %0, {%1, %2};" : "=l"(d) : "f"(lo), "f"(hi))
#define UNPACK2(lo, hi, s) asm("mov.b64 {%0, %1}, %2;" : "=f"(lo), "=f"(hi) : "l"(s))

// ---------------------------------------------------------------------------
// Pass 1 + fused finalize
// ---------------------------------------------------------------------------
__global__ void __launch_bounds__(BLOCK, 4) k_pass1(
    const float4* __restrict__ vox, const int* __restrict__ npts,
    const int4* __restrict__ coors, const float* __restrict__ Wm,
    const float* __restrict__ gm, const float* __restrict__ bt,
    float invNP, int N)
{
    const int lane = threadIdx.x & 31;
    const int wid  = threadIdx.x >> 5;
    const int warp = blockIdx.x * NWARP + wid;
    const int nwarps = GRID * NWARP;

    __shared__ float q_sm[NWARP][12];
    __shared__ float red[NWARP][NSTAT];

    float a[14];
#pragma unroll
    for (int i = 0; i < 14; i++) a[i] = 0.0f;
    float UQ[20];
#pragma unroll
    for (int i = 0; i < 20; i++) UQ[i] = 0.0f;
    float pv = 0.0f;
    const int ia = c_iA[lane], ib = c_iB[lane];

    for (int n = warp; n < N; n += nwarps) {
        const int k = __ldg(&npts[n]);
        if (k == 0) {
            if (lane == 0) g_meta[n] = make_float4(0.0f, 0.0f, 0.0f, 0.0f);
            continue;
        }
        const float4 v = vox[(size_t)n * 32 + lane];
        float4 u = v;
        if (lane >= k) { u.x = 0.f; u.y = 0.f; u.z = 0.f; u.w = 0.f; }

        // lane-private raw moments (valid points only)
        a[0]  += u.x;        a[1]  += u.y;        a[2]  += u.z;        a[3]  += u.w;
        a[4]  += u.x * u.x;  a[5]  += u.x * u.y;  a[6]  += u.x * u.z;  a[7]  += u.x * u.w;
        a[8]  += u.y * u.y;  a[9]  += u.y * u.z;  a[10] += u.y * u.w;
        a[11] += u.z * u.z;  a[12] += u.z * u.w;  a[13] += u.w * u.w;

        // unmasked all-point xyz sums -> cluster mean m (broadcast to all lanes)
        const float sa0 = wsum(v.x), sa1 = wsum(v.y), sa2 = wsum(v.z);
        const float kf = (float)k, inv = 1.0f / kf;
        const float m0 = sa0 * inv, m1 = sa1 * inv, m2 = sa2 * inv;
        const int4 cc = coors[n];
        const float px = (float)cc.y * 0.1f + (0.05f - 20.0f);
        const float py = (float)cc.z * 0.1f + (0.05f - 20.0f);

        // per-lane point contributions: U_ij += m_i u_j ; Q += p u_j
        UQ[0]  += m0 * u.x;  UQ[1]  += m0 * u.y;  UQ[2]  += m0 * u.z;  UQ[3]  += m0 * u.w;
        UQ[4]  += m1 * u.x;  UQ[5]  += m1 * u.y;  UQ[6]  += m1 * u.z;  UQ[7]  += m1 * u.w;
        UQ[8]  += m2 * u.x;  UQ[9]  += m2 * u.y;  UQ[10] += m2 * u.z;  UQ[11] += m2 * u.w;
        UQ[12] += px * u.x;  UQ[13] += px * u.y;  UQ[14] += px * u.z;  UQ[15] += px * u.w;
        UQ[16] += py * u.x;  UQ[17] += py * u.y;  UQ[18] += py * u.z;  UQ[19] += py * u.w;

        if (lane == 0) {
            float4* qs = (float4*)q_sm[wid];
            qs[0] = make_float4(m0, m1, m2, sa0);
            qs[1] = make_float4(sa1, sa2, px, py);
            qs[2] = make_float4(kf * px, kf * py, 1.0f, 0.0f);
            g_meta[n] = make_float4(m0, m1, m2, kf);
        }
        __syncwarp();
        pv = fmaf(q_sm[wid][ia], q_sm[wid][ib], pv);
        __syncwarp();
    }

    // end-of-kernel reductions
#pragma unroll
    for (int i = 0; i < 14; i++) a[i] = wsum(a[i]);
#pragma unroll
    for (int i = 0; i < 20; i++) UQ[i] = wsum(UQ[i]);
    if (lane == 0) {
#pragma unroll
        for (int i = 0; i < 14; i++) red[wid][i] = a[i];
#pragma unroll
        for (int i = 0; i < 20; i++) red[wid][14 + i] = UQ[i];   // U(12), Qx(4), Qy(4) -> 14..33
    }
    if (lane < 20) red[wid][34 + lane] = pv;
    __syncthreads();
    if (threadIdx.x < NSTAT) {
        float s = 0.0f;
#pragma unroll
        for (int w = 0; w < NWARP; w++) s += red[w][threadIdx.x];
        atomicAdd(&g_stats[threadIdx.x], s);
    }
    __threadfence();
    __shared__ unsigned s_last;
    if (threadIdx.x == 0) s_last = atomicAdd(&g_count, 1u);
    __syncthreads();
    if (s_last != GRID - 1) return;
    __threadfence();

    // ---------------- finalize (last block only) ----------------
    __shared__ float S[9];
    __shared__ float M[9][9];
    if (threadIdx.x == 0) {
        float st[NSTAT];
#pragma unroll
        for (int i = 0; i < NSTAT; i++) st[i] = __ldcg(&g_stats[i]);

        auto G2 = [&](int i, int j) -> float {
            if (i > j) { int t = i; i = j; j = t; }
            const int base[4] = {0, 4, 7, 9};
            return st[4 + base[i] + (j - i)];
        };
        auto U = [&](int i, int j) -> float { return st[14 + i * 4 + j]; };
        auto V = [&](int i, int j) -> float {
            int lo = i < j ? i : j, hi = i < j ? j : i;
            const int b3[3] = {0, 3, 5};
            return st[34 + b3[lo] + (hi - lo)];
        };
        const float* Qx = st + 26; const float* Qy = st + 30;
        const float* Wx = st + 40; const float* Wy = st + 43; const float* Ksa = st + 46;
        const float Rxx = st[49], Rxy = st[50], Ryy = st[51], Lx = st[52], Ly = st[53];

        S[0] = st[0]; S[1] = st[1]; S[2] = st[2]; S[3] = st[3];
        S[4] = st[0] - Ksa[0]; S[5] = st[1] - Ksa[1]; S[6] = st[2] - Ksa[2];
        S[7] = st[0] - Lx;     S[8] = st[1] - Ly;

        for (int i = 0; i < 4; i++)
            for (int j = 0; j < 4; j++) M[i][j] = G2(i, j);
        for (int j = 0; j < 3; j++)
            for (int i = 0; i < 4; i++) {
                const float m = G2(i, j) - U(j, i);
                M[i][4 + j] = m; M[4 + j][i] = m;
            }
        for (int i = 0; i < 3; i++)
            for (int j = 0; j < 3; j++)
                M[4 + i][4 + j] = G2(i, j) - U(i, j) - U(j, i) + V(i, j);
        for (int i = 0; i < 4; i++) {
            float m = G2(i, 0) - Qx[i]; M[i][7] = m; M[7][i] = m;
            m       = G2(i, 1) - Qy[i]; M[i][8] = m; M[8][i] = m;
        }
        for (int i = 0; i < 3; i++) {
            float m = G2(i, 0) - Qx[i] - U(i, 0) + Wx[i]; M[4 + i][7] = m; M[7][4 + i] = m;
            m       = G2(i, 1) - Qy[i] - U(i, 1) + Wy[i]; M[4 + i][8] = m; M[8][4 + i] = m;
        }
        M[7][7] = G2(0, 0) - 2.0f * Qx[0] + Rxx;
        M[7][8] = G2(0, 1) - Qx[1] - Qy[0] + Rxy; M[8][7] = M[7][8];
        M[8][8] = G2(1, 1) - 2.0f * Qy[1] + Ryy;
    }
    __syncthreads();

    // reset state for next graph replay
    if (threadIdx.x < NSTAT) g_stats[threadIdx.x] = 0.0f;
    if (threadIdx.x == 0)    g_count = 0u;

    const int o = threadIdx.x;
    if (o < 64) {
        float w[9];
#pragma unroll
        for (int j = 0; j < 9; j++) w[j] = Wm[o * 9 + j];
        float mean = 0.0f;
#pragma unroll
        for (int j = 0; j < 9; j++) mean += w[j] * S[j];
        mean *= invNP;
        float e2 = 0.0f;
#pragma unroll
        for (int i = 0; i < 9; i++) {
            float acc = 0.0f;
#pragma unroll
            for (int j = 0; j < 9; j++) acc += w[j] * M[i][j];
            e2 += w[i] * acc;
        }
        e2 *= invNP;
        const float var = e2 - mean * mean;
        const float sc  = gm[o] * rsqrtf(var + 1e-3f);
        const float sh  = bt[o] - mean * sc;

        g_params[0 * 64 + o] = sc * (w[0] + w[4] + w[7]);
        g_params[1 * 64 + o] = sc * (w[1] + w[5] + w[8]);
        g_params[2 * 64 + o] = sc * (w[2] + w[6]);
        g_params[3 * 64 + o] = sc * w[3];
        g_params[4 * 64 + o] = sc * w[4];
        g_params[5 * 64 + o] = sc * w[5];
        g_params[6 * 64 + o] = sc * w[6];
        g_params[7 * 64 + o] = sc * w[7];
        g_params[8 * 64 + o] = sc * w[8];
        g_params[9 * 64 + o] = sh;
    }
}

// ---------------------------------------------------------------------------
// Pass 2: warp per voxel; lane = channels (2*lane, 2*lane+1); points in SoA
// smem, processed 2-at-a-time with packed f32x2 FMAs.
// ---------------------------------------------------------------------------
__global__ void __launch_bounds__(BLOCK, 4) k_pass2(
    const float4* __restrict__ vox, const int4* __restrict__ coors,
    float2* __restrict__ out, int N)
{
    const int lane = threadIdx.x & 31;
    const int wid  = threadIdx.x >> 5;
    const int warp = blockIdx.x * NWARP + wid;
    const int nwarps = GRID * NWARP;
    const int c = lane * 2;

    const float A0a = g_params[0 * 64 + c], A0b = g_params[0 * 64 + c + 1];
    const float A1a = g_params[1 * 64 + c], A1b = g_params[1 * 64 + c + 1];
    const float A2a = g_params[2 * 64 + c], A2b = g_params[2 * 64 + c + 1];
    const float A3a = g_params[3 * 64 + c], A3b = g_params[3 * 64 + c + 1];
    const float B0a = g_params[4 * 64 + c], B0b = g_params[4 * 64 + c + 1];
    const float B1a = g_params[5 * 64 + c], B1b = g_params[5 * 64 + c + 1];
    const float B2a = g_params[6 * 64 + c], B2b = g_params[6 * 64 + c + 1];
    const float B3a = g_params[7 * 64 + c], B3b = g_params[7 * 64 + c + 1];
    const float B4a = g_params[8 * 64 + c], B4b = g_params[8 * 64 + c + 1];
    const float Ta  = g_params[9 * 64 + c], Tb  = g_params[9 * 64 + c + 1];

    uint64_t A0pa, A1pa, A2pa, A3pa, A0pb, A1pb, A2pb, A3pb;
    PACK2(A0pa, A0a, A0a); PACK2(A1pa, A1a, A1a); PACK2(A2pa, A2a, A2a); PACK2(A3pa, A3a, A3a);
    PACK2(A0pb, A0b, A0b); PACK2(A1pb, A1b, A1b); PACK2(A2pb, A2b, A2b); PACK2(A3pb, A3b, A3b);

    __shared__ float sx[NWARP][32], sy[NWARP][32], sz[NWARP][32], sw[NWARP][32];
    const float NEG_INF = __int_as_float(0xff800000);

    for (int n = warp; n < N; n += nwarps) {
        const float4 meta = g_meta[n];
        const int k = (int)meta.w;
        if (k == 0) {
            out[(size_t)n * 32 + lane] = make_float2(0.0f, 0.0f);
            continue;
        }
        const float4 u = vox[(size_t)n * 32 + lane];
        sx[wid][lane] = u.x; sy[wid][lane] = u.y; sz[wid][lane] = u.z; sw[wid][lane] = u.w;

        const int4 cc = coors[n];
        const float px = (float)cc.y * 0.1f + (0.05f - 20.0f);
        const float py = (float)cc.z * 0.1f + (0.05f - 20.0f);

        float ta = B0a * meta.x;    ta = fmaf(B1a, meta.y, ta);
        ta = fmaf(B2a, meta.z, ta); ta = fmaf(B3a, px, ta); ta = fmaf(B4a, py, ta);
        const float offa = Ta - ta;
        float tb = B0b * meta.x;    tb = fmaf(B1b, meta.y, tb);
        tb = fmaf(B2b, meta.z, tb); tb = fmaf(B3b, px, tb); tb = fmaf(B4b, py, tb);
        const float offb = Tb - tb;

        uint64_t OFFa, OFFb;
        PACK2(OFFa, offa, offa);
        PACK2(OFFb, offb, offb);

        __syncwarp();
        const uint64_t* X = (const uint64_t*)sx[wid];
        const uint64_t* Y = (const uint64_t*)sy[wid];
        const uint64_t* Z = (const uint64_t*)sz[wid];
        const uint64_t* W = (const uint64_t*)sw[wid];

        float ra0 = NEG_INF, ra1 = NEG_INF, rb0 = NEG_INF, rb1 = NEG_INF;
        const int np = k >> 1;
#pragma unroll 4
        for (int j = 0; j < np; j++) {
            const uint64_t x2 = X[j], y2 = Y[j], z2 = Z[j], w2 = W[j];
            uint64_t t;
            float lo, hi;
            FMA2(t, w2, A3pa, OFFa); FMA2(t, z2, A2pa, t); FMA2(t, y2, A1pa, t); FMA2(t, x2, A0pa, t);
            UNPACK2(lo, hi, t);
            ra0 = fmaxf(ra0, lo); ra1 = fmaxf(ra1, hi);
            FMA2(t, w2, A3pb, OFFb); FMA2(t, z2, A2pb, t); FMA2(t, y2, A1pb, t); FMA2(t, x2, A0pb, t);
            UNPACK2(lo, hi, t);
            rb0 = fmaxf(rb0, lo); rb1 = fmaxf(rb1, hi);
        }
        if (k & 1) {
            const int p = k - 1;
            const float x = sx[wid][p], y = sy[wid][p], z = sz[wid][p], w = sw[wid][p];
            const float ya = fmaf(x, A0a, fmaf(y, A1a, fmaf(z, A2a, fmaf(w, A3a, offa))));
            const float yb = fmaf(x, A0b, fmaf(y, A1b, fmaf(z, A2b, fmaf(w, A3b, offb))));
            ra0 = fmaxf(ra0, ya);
            rb0 = fmaxf(rb0, yb);
        }
        const float ra = fmaxf(fmaxf(ra0, ra1), 0.0f);
        const float rb = fmaxf(fmaxf(rb0, rb1), 0.0f);
        out[(size_t)n * 32 + lane] = make_float2(ra, rb);
        __syncwarp();
    }
}

// ---------------------------------------------------------------------------
extern "C" void kernel_launch(void* const* d_in, const int* in_sizes, int n_in,
                              void* d_out, int out_size)
{
    const float* voxels = (const float*)d_in[0];
    const int*   npts   = (const int*)d_in[1];
    const int*   coors  = (const int*)d_in[2];
    const float* W      = (const float*)d_in[3];
    const float* gamma  = (const float*)d_in[4];
    const float* beta   = (const float*)d_in[5];
    float*       out    = (float*)d_out;
    const int N = in_sizes[1];

    k_pass1<<<GRID, BLOCK>>>((const float4*)voxels, npts, (const int4*)coors,
                             W, gamma, beta, 1.0f / ((float)N * 32.0f), N);
    k_pass2<<<GRID, BLOCK>>>((const float4*)voxels, (const int4*)coors,
                             (float2*)out, N);
}